// round 6
// baseline (speedup 1.0000x reference)
#include <cuda_runtime.h>
#include <cuda_bf16.h>
#include <cstdint>
#include <math.h>

#define BB 48
#define SS 128
#define WW 4
#define KK 256
#define KH 128
#define NT 512

typedef unsigned long long ull;

#define FMA2(acc, a, b) \
    asm("fma.rn.f32x2 %0, %1, %2, %0;" : "+l"(acc) : "l"(a), "l"(b))
#define UNPACK2(lo, hi, p) \
    asm("mov.b64 {%0, %1}, %2;" : "=f"(lo), "=f"(hi) : "l"(p))
#define DUP2(d, f) \
    asm("mov.b64 %0, {%1, %1};" : "=l"(d) : "f"(f))

static __device__ __forceinline__ uint32_t s2u(const void* p) {
    uint32_t a;
    asm("{ .reg .u64 t; cvta.to.shared.u64 t, %1; cvt.u32.u64 %0, t; }"
        : "=r"(a) : "l"(p));
    return a;
}
static __device__ __forceinline__ uint32_t mapa_u(uint32_t a, int rk) {
    uint32_t r;
    asm("mapa.shared::cluster.u32 %0, %1, %2;" : "=r"(r) : "r"(a), "r"(rk));
    return r;
}
static __device__ __forceinline__ void mbar_init(uint32_t mb, uint32_t cnt) {
    asm volatile("mbarrier.init.shared.b64 [%0], %1;" :: "r"(mb), "r"(cnt) : "memory");
}
static __device__ __forceinline__ void arrive_remote(uint32_t mb) {
    asm volatile("mbarrier.arrive.release.cluster.shared::cluster.b64 _, [%0];"
                 :: "r"(mb) : "memory");
}
static __device__ __forceinline__ void wait_parity(uint32_t mb, uint32_t par) {
    asm volatile(
        "{\n\t.reg .pred P;\n\t"
        "W_%=:\n\t"
        "mbarrier.try_wait.parity.acquire.cluster.shared::cta.b64 P, [%0], %1, 0x989680;\n\t"
        "@!P bra W_%=;\n\t}"
        :: "r"(mb), "r"(par) : "memory");
}
static __device__ __forceinline__ void st_cluster_f32(uint32_t a, float v) {
    asm volatile("st.shared::cluster.f32 [%0], %1;" :: "r"(a), "f"(v) : "memory");
}

extern "C" __global__ void __launch_bounds__(NT, 1) __cluster_dims__(2, 1, 1)
crf_cluster_kernel(const float* __restrict__ logits,
                   const float* __restrict__ T,
                   const float* __restrict__ hc,
                   const float* __restrict__ tagm,
                   const int*   __restrict__ textmask,
                   float* __restrict__ out)
{
    __shared__ float4 sVd[KK];        // (v0,v1,v2,v3) per kp
    __shared__ float4 sPart[8][KH];   // per-kp-slice partial dots
    __shared__ float  sRing[8][KK];   // alpha history ring (full rows)
    __shared__ float  sPmax[8][4];    // peer warp-maxes per slot
    __shared__ float  sRed[32];
    __shared__ ull    sMbar[8];

    const int tid  = threadIdx.x;
    const int lane = tid & 31;
    const int wid  = tid >> 5;
    const int b    = blockIdx.x >> 1;
    const int r    = blockIdx.x & 1;
    const int s    = tid >> 6;        // kp slice 0..7 (32 kp each)
    const int p    = tid & 63;        // k-pair within my half

    // ---- length[b] ----
    {
        int t = (tid < SS) ? textmask[b * SS + tid] : 0;
        #pragma unroll
        for (int o = 16; o; o >>= 1) t += __shfl_xor_sync(0xffffffffu, t, o);
        if (lane == 0) sRed[wid] = (float)t;
    }
    __syncthreads();
    int L = 0;
    #pragma unroll
    for (int i = 0; i < 16; i++) L += (int)sRed[i];
    __syncthreads();
    if (L == 0) { if (r == 0 && tid == 0) out[b] = logf(256.0f); return; }
    const int JMAX = (L < SS) ? L : SS;

    // ---- mbarriers + cluster handshake ----
    if (tid < 8) mbar_init(s2u(&sMbar[tid]), 128);
    __syncthreads();
    asm volatile("barrier.cluster.arrive.aligned;" ::: "memory");
    asm volatile("barrier.cluster.wait.aligned;"   ::: "memory");

    const int      peer     = 1 - r;
    const uint32_t myMbar   = s2u(sMbar);
    const uint32_t peerRing = mapa_u(s2u(sRing), peer);
    const uint32_t peerPmax = mapa_u(s2u(sPmax), peer);
    const uint32_t peerMbar = mapa_u(myMbar, peer);

    // ---- T slice into registers as bf16x2 (k0,k1) pairs: 32 regs ----
    uint32_t Treg[32];
    {
        const size_t rb = ((size_t)b * KK + (size_t)(r * KH)) * KK;
        const int k0 = 2 * p, k1 = 2 * p + 1, kp0 = 32 * s;
        const float4* Ta = (const float4*)(T    + rb + (size_t)k0 * KK + kp0);
        const float4* Ma = (const float4*)(tagm + rb + (size_t)k0 * KK + kp0);
        const float4* Tb = (const float4*)(T    + rb + (size_t)k1 * KK + kp0);
        const float4* Mb = (const float4*)(tagm + rb + (size_t)k1 * KK + kp0);
        #pragma unroll
        for (int q = 0; q < 8; q++) {
            float4 tv = __ldg(Ta + q), mv = __ldg(Ma + q);
            float4 tw = __ldg(Tb + q), mw = __ldg(Mb + q);
            float a0 = __expf(tv.x * mv.x), b0 = __expf(tw.x * mw.x);
            float a1 = __expf(tv.y * mv.y), b1 = __expf(tw.y * mw.y);
            float a2 = __expf(tv.z * mv.z), b2 = __expf(tw.z * mw.z);
            float a3 = __expf(tv.w * mv.w), b3 = __expf(tw.w * mw.w);
            __nv_bfloat162 p0 = __floats2bfloat162_rn(a0, b0);
            __nv_bfloat162 p1 = __floats2bfloat162_rn(a1, b1);
            __nv_bfloat162 p2 = __floats2bfloat162_rn(a2, b2);
            __nv_bfloat162 p3 = __floats2bfloat162_rn(a3, b3);
            Treg[4 * q + 0] = *(uint32_t*)&p0;
            Treg[4 * q + 1] = *(uint32_t*)&p1;
            Treg[4 * q + 2] = *(uint32_t*)&p2;
            Treg[4 * q + 3] = *(uint32_t*)&p3;
        }
    }

    const int kg = r * KH + tid;              // my global k (tid<128)
    const float tm0 = (tid < KH) ? tagm[(size_t)b * KK * KK + kg] : 0.f;

    float m0 = 0.f, m1 = 0.f, m2 = 0.f, m3 = 0.f;   // rowmax history (warps 0-7)

    for (int j = 0; j < JMAX; j++) {
        const int nT = (j < WW) ? j : WW;

        // ---- phase A: M and v rows (warps 0-7) ----
        float M = (j < WW) ? 0.0f : -1e30f;
        if (nT > 0) M = fmaxf(M, m0);
        if (nT > 1) M = fmaxf(M, m1);
        if (nT > 2) M = fmaxf(M, m2);
        if (nT > 3) M = fmaxf(M, m3);
        if (tid < KK) {
            float v0 = 0.f, v1 = 0.f, v2 = 0.f, v3 = 0.f;
            if (nT > 0) v0 = __expf(sRing[(j - 1) & 7][tid] - m0);
            if (nT > 1) v1 = __expf(sRing[(j - 2) & 7][tid] - m1);
            if (nT > 2) v2 = __expf(sRing[(j - 3) & 7][tid] - m2);
            if (nT > 3) v3 = __expf(sRing[(j - 4) & 7][tid] - m3);
            sVd[tid] = make_float4(v0, v1, v2, v3);
        }

        // ---- current-step emission loads (land during matvec) ----
        float l0 = 0.f, l1 = 0.f, l2 = 0.f, l3 = 0.f;
        float q0 = 0.f, q1 = 0.f, q2 = 0.f, q3 = 0.f;
        if (tid < KH) {
            const size_t ei = (((size_t)b * SS + j) * WW) * KK + kg;
            l0 = __ldg(logits + ei);          q0 = __ldg(hc + ei);
            l1 = __ldg(logits + ei + 1 * KK); q1 = __ldg(hc + ei + 1 * KK);
            l2 = __ldg(logits + ei + 2 * KK); q2 = __ldg(hc + ei + 2 * KK);
            l3 = __ldg(logits + ei + 3 * KK); q3 = __ldg(hc + ei + 3 * KK);
        }
        __syncthreads();

        // ---- phase B: register mat-vec, bf16 T, w-packed FFMA2 ----
        ull a01_0 = 0, a23_0 = 0, a01_1 = 0, a23_1 = 0;
        {
            const ulonglong2* vb = (const ulonglong2*)&sVd[s << 5];
            #pragma unroll
            for (int i = 0; i < 32; i++) {
                ulonglong2 vd = vb[i];               // broadcast LDS.128
                uint32_t tp = Treg[i];
                float f0 = __uint_as_float(tp << 16);          // k0
                float f1 = __uint_as_float(tp & 0xffff0000u);  // k1
                ull t0d, t1d;
                DUP2(t0d, f0);
                DUP2(t1d, f1);
                FMA2(a01_0, t0d, vd.x);  FMA2(a23_0, t0d, vd.y);
                FMA2(a01_1, t1d, vd.x);  FMA2(a23_1, t1d, vd.y);
            }
        }
        {
            float f0, f1, f2, f3;
            UNPACK2(f0, f1, a01_0); UNPACK2(f2, f3, a23_0);
            sPart[s][2 * p]     = make_float4(f0, f1, f2, f3);
            UNPACK2(f0, f1, a01_1); UNPACK2(f2, f3, a23_1);
            sPart[s][2 * p + 1] = make_float4(f0, f1, f2, f3);
        }
        __syncthreads();

        const int slot = j & 7;
        if (tid < KK) {   // warps 0-7: combine / exchange / rowmax
            float aN = 0.f, wmax = -1e30f;
            if (tid < KH) {
                float4 aw = sPart[0][tid];
                #pragma unroll
                for (int ss2 = 1; ss2 < 8; ss2++) {
                    float4 t4 = sPart[ss2][tid];
                    aw.x += t4.x; aw.y += t4.y; aw.z += t4.z; aw.w += t4.w;
                }
                const float e0 = (l0 + q0) * tm0, e1 = (l1 + q1) * tm0;
                const float e2 = (l2 + q2) * tm0, e3 = (l3 + q3) * tm0;
                float tot = 0.0f;
                if (nT > 0) tot += __expf(e0 + m0 - M) * aw.x;
                if (nT > 1) tot += __expf(e1 + m1 - M) * aw.y;
                if (nT > 2) tot += __expf(e2 + m2 - M) * aw.z;
                if (nT > 3) tot += __expf(e3 + m3 - M) * aw.w;
                if (j < WW) {
                    float ein = (j == 0) ? e0 : (j == 1) ? e1 : (j == 2) ? e2 : e3;
                    tot += 256.0f * __expf(ein - M);
                }
                aN = M + __logf(tot);

                // local ring + register->peer push, then per-lane arrive
                sRing[slot][kg] = aN;
                st_cluster_f32(peerRing + ((uint32_t)(slot * KK + kg)) * 4u, aN);
                if (lane != 0) arrive_remote(peerMbar + (uint32_t)slot * 8u);

                // warp max (overlaps the DSMEM flight)
                float mv = aN;
                #pragma unroll
                for (int o = 16; o; o >>= 1)
                    mv = fmaxf(mv, __shfl_xor_sync(0xffffffffu, mv, o));
                if (lane == 0) {
                    sRed[wid] = mv;
                    st_cluster_f32(peerPmax + ((uint32_t)(slot * 4 + wid)) * 4u, mv);
                    arrive_remote(peerMbar + (uint32_t)slot * 8u);
                }
            }
            asm volatile("bar.sync 1, 256;" ::: "memory");
            wait_parity(myMbar + (uint32_t)slot * 8u, (uint32_t)((j >> 3) & 1));

            float rowmax = fmaxf(fmaxf(sRed[0], sRed[1]), fmaxf(sRed[2], sRed[3]));
            rowmax = fmaxf(rowmax, fmaxf(fmaxf(sPmax[slot][0], sPmax[slot][1]),
                                         fmaxf(sPmax[slot][2], sPmax[slot][3])));
            m3 = m2; m2 = m1; m1 = m0; m0 = rowmax;

            if (j + 1 == JMAX) {   // final logsumexp over full alpha row
                float sv = __expf(sRing[slot][tid] - rowmax);
                #pragma unroll
                for (int o = 16; o; o >>= 1)
                    sv += __shfl_xor_sync(0xffffffffu, sv, o);
                if (lane == 0) sRed[8 + wid] = sv;
                asm volatile("bar.sync 1, 256;" ::: "memory");
                if (r == 0 && tid == 0) {
                    float ssum = 0.f;
                    #pragma unroll
                    for (int i = 0; i < 8; i++) ssum += sRed[8 + i];
                    out[b] = rowmax + __logf(ssum);
                }
            }
        }
    }

    // no CTA exits while peer stores may be in flight
    asm volatile("barrier.cluster.arrive.aligned;" ::: "memory");
    asm volatile("barrier.cluster.wait.aligned;"   ::: "memory");
}

// ---------------------------------------------------------------------------
extern "C" void kernel_launch(void* const* d_in, const int* in_sizes, int n_in,
                              void* d_out, int out_size) {
    const float* logits = (const float*)d_in[0];   // (B,S,W,K) f32
    const float* T      = (const float*)d_in[1];   // (B,K,K)   f32
    const float* hc     = (const float*)d_in[2];   // (B,S,W,K) f32
    const float* tagm   = (const float*)d_in[3];   // (B,K,K)   f32
    const int*   tmask  = (const int*)  d_in[4];   // (B,S)     i32
    float* out = (float*)d_out;                    // (1,B)     f32

    crf_cluster_kernel<<<BB * 2, NT>>>(logits, T, hc, tagm, tmask, out);
}

// round 7
// speedup vs baseline: 1.3133x; 1.3133x over previous
#include <cuda_runtime.h>
#include <cuda_bf16.h>
#include <cstdint>
#include <math.h>

#define BB 48
#define SS 128
#define WW 4
#define KK 256
#define KH 128
#define NT 512
#define TXB 528u    // 132 floats: 128 alphas + 4 warp maxes

typedef unsigned long long ull;

#define FMA2(acc, a, b) \
    asm("fma.rn.f32x2 %0, %1, %2, %0;" : "+l"(acc) : "l"(a), "l"(b))
#define UNPACK2(lo, hi, p) \
    asm("mov.b64 {%0, %1}, %2;" : "=f"(lo), "=f"(hi) : "l"(p))
#define DUP2(d, f) \
    asm("mov.b64 %0, {%1, %1};" : "=l"(d) : "f"(f))

static __device__ __forceinline__ uint32_t s2u(const void* p) {
    uint32_t a;
    asm("{ .reg .u64 t; cvta.to.shared.u64 t, %1; cvt.u32.u64 %0, t; }"
        : "=r"(a) : "l"(p));
    return a;
}
static __device__ __forceinline__ uint32_t mapa_u(uint32_t a, int rk) {
    uint32_t r;
    asm("mapa.shared::cluster.u32 %0, %1, %2;" : "=r"(r) : "r"(a), "r"(rk));
    return r;
}
static __device__ __forceinline__ void mbar_init(uint32_t mb, uint32_t cnt) {
    asm volatile("mbarrier.init.shared.b64 [%0], %1;" :: "r"(mb), "r"(cnt) : "memory");
}
static __device__ __forceinline__ void mbar_arm(uint32_t mb, uint32_t tx) {
    asm volatile("mbarrier.arrive.expect_tx.shared.b64 _, [%0], %1;"
                 :: "r"(mb), "r"(tx) : "memory");
}
static __device__ __forceinline__ void st_async_f32(uint32_t dst, float v, uint32_t mb) {
    asm volatile(
        "st.async.weak.shared::cluster.mbarrier::complete_tx::bytes.f32 [%0], %1, [%2];"
        :: "r"(dst), "f"(v), "r"(mb) : "memory");
}
static __device__ __forceinline__ void wait_parity(uint32_t mb, uint32_t par) {
    asm volatile(
        "{\n\t.reg .pred P;\n\t"
        "W_%=:\n\t"
        "mbarrier.try_wait.parity.acquire.cluster.shared::cta.b64 P, [%0], %1, 0x989680;\n\t"
        "@!P bra W_%=;\n\t}"
        :: "r"(mb), "r"(par) : "memory");
}

extern "C" __global__ void __launch_bounds__(NT, 1) __cluster_dims__(2, 1, 1)
crf_cluster_kernel(const float* __restrict__ logits,
                   const float* __restrict__ T,
                   const float* __restrict__ hc,
                   const float* __restrict__ tagm,
                   const int*   __restrict__ textmask,
                   float* __restrict__ out)
{
    __shared__ float4 sVd[KK];        // (v0,v1,v2,v3) per kp
    __shared__ float4 sPart[8][KH];   // per-kp-slice partial dots
    __shared__ float  sRing[8][KK];   // alpha history ring (full rows)
    __shared__ float  sPmax[8][4];    // peer warp-maxes per slot
    __shared__ float  sRed[32];
    __shared__ ull    sMbar[8];

    const int tid  = threadIdx.x;
    const int lane = tid & 31;
    const int wid  = tid >> 5;
    const int b    = blockIdx.x >> 1;
    const int r    = blockIdx.x & 1;
    const int s    = tid >> 6;        // kp slice 0..7 (32 kp each)
    const int p    = tid & 63;        // k-pair within my half

    // ---- length[b] ----
    {
        int t = (tid < SS) ? textmask[b * SS + tid] : 0;
        #pragma unroll
        for (int o = 16; o; o >>= 1) t += __shfl_xor_sync(0xffffffffu, t, o);
        if (lane == 0) sRed[wid] = (float)t;
    }
    __syncthreads();
    int L = 0;
    #pragma unroll
    for (int i = 0; i < 16; i++) L += (int)sRed[i];
    __syncthreads();
    if (L == 0) { if (r == 0 && tid == 0) out[b] = logf(256.0f); return; }
    const int JMAX = (L < SS) ? L : SS;

    // ---- mbarriers: count=1/phase; arm all 8 slots for their first phase ----
    if (tid < 8) {
        mbar_init(s2u(&sMbar[tid]), 1);
        mbar_arm(s2u(&sMbar[tid]), TXB);
    }
    __syncthreads();
    asm volatile("barrier.cluster.arrive.aligned;" ::: "memory");
    asm volatile("barrier.cluster.wait.aligned;"   ::: "memory");

    const int      peer     = 1 - r;
    const uint32_t myMbar   = s2u(sMbar);
    const uint32_t peerRing = mapa_u(s2u(sRing), peer);
    const uint32_t peerPmax = mapa_u(s2u(sPmax), peer);
    const uint32_t peerMbar = mapa_u(myMbar, peer);

    // ---- T slice into registers as bf16x2 (k0,k1) pairs: 32 regs ----
    uint32_t Treg[32];
    {
        const size_t rb = ((size_t)b * KK + (size_t)(r * KH)) * KK;
        const int k0 = 2 * p, k1 = 2 * p + 1, kp0 = 32 * s;
        const float4* Ta = (const float4*)(T    + rb + (size_t)k0 * KK + kp0);
        const float4* Ma = (const float4*)(tagm + rb + (size_t)k0 * KK + kp0);
        const float4* Tb = (const float4*)(T    + rb + (size_t)k1 * KK + kp0);
        const float4* Mb = (const float4*)(tagm + rb + (size_t)k1 * KK + kp0);
        #pragma unroll
        for (int q = 0; q < 8; q++) {
            float4 tv = __ldg(Ta + q), mv = __ldg(Ma + q);
            float4 tw = __ldg(Tb + q), mw = __ldg(Mb + q);
            __nv_bfloat162 p0 = __floats2bfloat162_rn(__expf(tv.x * mv.x), __expf(tw.x * mw.x));
            __nv_bfloat162 p1 = __floats2bfloat162_rn(__expf(tv.y * mv.y), __expf(tw.y * mw.y));
            __nv_bfloat162 p2 = __floats2bfloat162_rn(__expf(tv.z * mv.z), __expf(tw.z * mw.z));
            __nv_bfloat162 p3 = __floats2bfloat162_rn(__expf(tv.w * mv.w), __expf(tw.w * mw.w));
            Treg[4 * q + 0] = *(uint32_t*)&p0;
            Treg[4 * q + 1] = *(uint32_t*)&p1;
            Treg[4 * q + 2] = *(uint32_t*)&p2;
            Treg[4 * q + 3] = *(uint32_t*)&p3;
        }
    }

    const int kg = r * KH + tid;              // my global k (tid<128)
    const float tm0 = (tid < KH) ? tagm[(size_t)b * KK * KK + kg] : 0.f;

    float m0 = 0.f, m1 = 0.f, m2 = 0.f, m3 = 0.f;   // rowmax history (warps 0-7)

    for (int j = 0; j < JMAX; j++) {
        const int nT = (j < WW) ? j : WW;
        const int slot = j & 7;

        // ---- phase A: M and v rows (warps 0-7) ----
        float M = (j < WW) ? 0.0f : -1e30f;
        if (nT > 0) M = fmaxf(M, m0);
        if (nT > 1) M = fmaxf(M, m1);
        if (nT > 2) M = fmaxf(M, m2);
        if (nT > 3) M = fmaxf(M, m3);
        if (tid < KK) {
            float v0 = 0.f, v1 = 0.f, v2 = 0.f, v3 = 0.f;
            if (nT > 0) v0 = __expf(sRing[(j - 1) & 7][tid] - m0);
            if (nT > 1) v1 = __expf(sRing[(j - 2) & 7][tid] - m1);
            if (nT > 2) v2 = __expf(sRing[(j - 3) & 7][tid] - m2);
            if (nT > 3) v3 = __expf(sRing[(j - 4) & 7][tid] - m3);
            sVd[tid] = make_float4(v0, v1, v2, v3);
        }

        // ---- current-step emission loads (land during matvec) ----
        float l0 = 0.f, l1 = 0.f, l2 = 0.f, l3 = 0.f;
        float q0 = 0.f, q1 = 0.f, q2 = 0.f, q3 = 0.f;
        if (tid < KH) {
            const size_t ei = (((size_t)b * SS + j) * WW) * KK + kg;
            l0 = __ldg(logits + ei);          q0 = __ldg(hc + ei);
            l1 = __ldg(logits + ei + 1 * KK); q1 = __ldg(hc + ei + 1 * KK);
            l2 = __ldg(logits + ei + 2 * KK); q2 = __ldg(hc + ei + 2 * KK);
            l3 = __ldg(logits + ei + 3 * KK); q3 = __ldg(hc + ei + 3 * KK);
        }
        __syncthreads();

        // ---- phase B: register mat-vec, bf16 T, w-packed FFMA2 ----
        ull a01_0 = 0, a23_0 = 0, a01_1 = 0, a23_1 = 0;
        {
            const ulonglong2* vb = (const ulonglong2*)&sVd[s << 5];
            #pragma unroll
            for (int i = 0; i < 32; i++) {
                ulonglong2 vd = vb[i];               // warp-uniform LDS.128
                uint32_t tp = Treg[i];
                float f0 = __uint_as_float(tp << 16);          // k0
                float f1 = __uint_as_float(tp & 0xffff0000u);  // k1
                ull t0d, t1d;
                DUP2(t0d, f0);
                DUP2(t1d, f1);
                FMA2(a01_0, t0d, vd.x);  FMA2(a23_0, t0d, vd.y);
                FMA2(a01_1, t1d, vd.x);  FMA2(a23_1, t1d, vd.y);
            }
        }
        {
            float f0, f1, f2, f3;
            UNPACK2(f0, f1, a01_0); UNPACK2(f2, f3, a23_0);
            sPart[s][2 * p]     = make_float4(f0, f1, f2, f3);
            UNPACK2(f0, f1, a01_1); UNPACK2(f2, f3, a23_1);
            sPart[s][2 * p + 1] = make_float4(f0, f1, f2, f3);
        }
        __syncthreads();

        if (tid < KK) {   // warps 0-7: combine, push via st.async, rowmax
            if (tid < KH) {
                float4 aw = sPart[0][tid];
                #pragma unroll
                for (int ss2 = 1; ss2 < 8; ss2++) {
                    float4 t4 = sPart[ss2][tid];
                    aw.x += t4.x; aw.y += t4.y; aw.z += t4.z; aw.w += t4.w;
                }
                const float e0 = (l0 + q0) * tm0, e1 = (l1 + q1) * tm0;
                const float e2 = (l2 + q2) * tm0, e3 = (l3 + q3) * tm0;
                float tot = 0.0f;
                if (nT > 0) tot += __expf(e0 + m0 - M) * aw.x;
                if (nT > 1) tot += __expf(e1 + m1 - M) * aw.y;
                if (nT > 2) tot += __expf(e2 + m2 - M) * aw.z;
                if (nT > 3) tot += __expf(e3 + m3 - M) * aw.w;
                if (j < WW) {
                    float ein = (j == 0) ? e0 : (j == 1) ? e1 : (j == 2) ? e2 : e3;
                    tot += 256.0f * __expf(ein - M);
                }
                const float aN = M + __logf(tot);

                // local ring + async push to peer (completion rides the store)
                sRing[slot][kg] = aN;
                st_async_f32(peerRing + ((uint32_t)(slot * KK + kg)) * 4u, aN,
                             peerMbar + (uint32_t)slot * 8u);

                // warp max, then push it on the same barrier
                float mv = aN;
                #pragma unroll
                for (int o = 16; o; o >>= 1)
                    mv = fmaxf(mv, __shfl_xor_sync(0xffffffffu, mv, o));
                if (lane == 0) {
                    sRed[wid] = mv;
                    st_async_f32(peerPmax + ((uint32_t)(slot * 4 + wid)) * 4u, mv,
                                 peerMbar + (uint32_t)slot * 8u);
                }
            }
            asm volatile("bar.sync 1, 256;" ::: "memory");
            wait_parity(myMbar + (uint32_t)slot * 8u, (uint32_t)((j >> 3) & 1));

            float rowmax = fmaxf(fmaxf(sRed[0], sRed[1]), fmaxf(sRed[2], sRed[3]));
            rowmax = fmaxf(rowmax, fmaxf(fmaxf(sPmax[slot][0], sPmax[slot][1]),
                                         fmaxf(sPmax[slot][2], sPmax[slot][3])));
            m3 = m2; m2 = m1; m1 = m0; m0 = rowmax;

            // re-arm this slot for its next phase (used again at step j+8;
            // peer can't reach it for >= 7 steps, so this is race-free)
            if (tid == 0) mbar_arm(myMbar + (uint32_t)slot * 8u, TXB);

            if (j + 1 == JMAX) {   // final logsumexp over full alpha row
                float sv = __expf(sRing[slot][tid] - rowmax);
                #pragma unroll
                for (int o = 16; o; o >>= 1)
                    sv += __shfl_xor_sync(0xffffffffu, sv, o);
                if (lane == 0) sRed[8 + wid] = sv;
                asm volatile("bar.sync 1, 256;" ::: "memory");
                if (r == 0 && tid == 0) {
                    float ssum = 0.f;
                    #pragma unroll
                    for (int i = 0; i < 8; i++) ssum += sRed[8 + i];
                    out[b] = rowmax + __logf(ssum);
                }
            }
        }
    }

    // no CTA exits while peer stores may be in flight
    asm volatile("barrier.cluster.arrive.aligned;" ::: "memory");
    asm volatile("barrier.cluster.wait.aligned;"   ::: "memory");
}

// ---------------------------------------------------------------------------
extern "C" void kernel_launch(void* const* d_in, const int* in_sizes, int n_in,
                              void* d_out, int out_size) {
    const float* logits = (const float*)d_in[0];   // (B,S,W,K) f32
    const float* T      = (const float*)d_in[1];   // (B,K,K)   f32
    const float* hc     = (const float*)d_in[2];   // (B,S,W,K) f32
    const float* tagm   = (const float*)d_in[3];   // (B,K,K)   f32
    const int*   tmask  = (const int*)  d_in[4];   // (B,S)     i32
    float* out = (float*)d_out;                    // (1,B)     f32

    crf_cluster_kernel<<<BB * 2, NT>>>(logits, T, hc, tagm, tmask, out);
}

// round 8
// speedup vs baseline: 1.5540x; 1.1833x over previous
#include <cuda_runtime.h>
#include <cuda_bf16.h>
#include <cstdint>
#include <math.h>

#define BB 48
#define SS 128
#define WW 4
#define KK 256
#define NT 512
#define NCH 16          // K chunks of 16
#define ROWB 520        // v_sm row stride in bytes (padded vs 512 to dodge conflicts)

#define MMA_BF16(d0, d1, d2, d3, a, b0, b1)                                   \
    asm volatile(                                                             \
        "mma.sync.aligned.m16n8k16.row.col.f32.bf16.bf16.f32 "                \
        "{%0,%1,%2,%3}, {%4,%5,%6,%7}, {%8,%9}, {%0,%1,%2,%3};"               \
        : "+f"(d0), "+f"(d1), "+f"(d2), "+f"(d3)                              \
        : "r"((a)[0]), "r"((a)[1]), "r"((a)[2]), "r"((a)[3]),                 \
          "r"(b0), "r"(b1))

__global__ void __launch_bounds__(NT, 1)
crf_hmma_kernel(const float* __restrict__ logits,
                const float* __restrict__ T,
                const float* __restrict__ hc,
                const float* __restrict__ tagm,
                const int*   __restrict__ textmask,
                float* __restrict__ out)
{
    __shared__ float  sRing[8][KK];     // alpha history ring
    __shared__ float4 sE[KK];           // staged emissions for current step
    __shared__ float  sRed[32];         // [0..15] warp maxes, [16..23] final sums
    __shared__ __align__(4) unsigned char vsm[4 * ROWB];   // v (bf16), rows n=0..3

    const int tid  = threadIdx.x;
    const int lane = tid & 31;
    const int wid  = tid >> 5;
    const int b    = blockIdx.x;

    // ---- length[b] ----
    {
        int t = (tid < SS) ? textmask[b * SS + tid] : 0;
        #pragma unroll
        for (int o = 16; o; o >>= 1) t += __shfl_xor_sync(0xffffffffu, t, o);
        if (lane == 0) sRed[wid] = (float)t;
    }
    __syncthreads();
    int L = 0;
    #pragma unroll
    for (int i = 0; i < 16; i++) L += (int)sRed[i];
    __syncthreads();
    if (L == 0) { if (tid == 0) out[b] = logf(256.0f); return; }
    const int JMAX = (L < SS) ? L : SS;

    // ---- prologue: A = bf16(exp(T*mask)) fragments in registers ----
    // warp owns M-rows [16*wid, 16*wid+16); thread rows r0g, r0g+8
    const size_t tb  = (size_t)b * KK * KK;
    const int    r0g = (wid << 4) + (lane >> 2);
    const int    kq  = (lane & 3) << 1;
    uint32_t A[NCH][4];
    {
        const float* Tr0 = T    + tb + (size_t)r0g * KK;
        const float* Mr0 = tagm + tb + (size_t)r0g * KK;
        const float* Tr1 = Tr0 + 8 * KK;
        const float* Mr1 = Mr0 + 8 * KK;
        #pragma unroll
        for (int c = 0; c < NCH; c++) {
            #pragma unroll
            for (int h = 0; h < 2; h++) {
                const int kk2 = c * 16 + kq + h * 8;
                float2 t0 = *(const float2*)(Tr0 + kk2);
                float2 m0 = *(const float2*)(Mr0 + kk2);
                float2 t1 = *(const float2*)(Tr1 + kk2);
                float2 m1 = *(const float2*)(Mr1 + kk2);
                __nv_bfloat162 p0 =
                    __floats2bfloat162_rn(__expf(t0.x * m0.x), __expf(t0.y * m0.y));
                __nv_bfloat162 p1 =
                    __floats2bfloat162_rn(__expf(t1.x * m1.x), __expf(t1.y * m1.y));
                A[c][h * 2 + 0] = *(uint32_t*)&p0;   // row r0g,   k-block h
                A[c][h * 2 + 1] = *(uint32_t*)&p1;   // row r0g+8, k-block h
            }
        }
    }

    // ---- stage emissions for j = 0 ----
    const float tm0 = (tid < KK) ? tagm[tb + tid] : 0.f;
    if (tid < KK) {
        const size_t ei = ((size_t)b * SS) * WW * KK + tid;
        float e0 = (__ldg(logits + ei         ) + __ldg(hc + ei         )) * tm0;
        float e1 = (__ldg(logits + ei + 1 * KK) + __ldg(hc + ei + 1 * KK)) * tm0;
        float e2 = (__ldg(logits + ei + 2 * KK) + __ldg(hc + ei + 2 * KK)) * tm0;
        float e3 = (__ldg(logits + ei + 3 * KK) + __ldg(hc + ei + 3 * KK)) * tm0;
        sE[tid] = make_float4(e0, e1, e2, e3);
    }
    float m0 = 0.f, m1 = 0.f, m2 = 0.f, m3 = 0.f;   // rowmax history
    __syncthreads();

    for (int j = 0; j < JMAX; j++) {
        const int nT   = (j < WW) ? j : WW;
        const int slot = j & 7;

        float M = (j < WW) ? 0.0f : -1e30f;
        if (nT > 0) M = fmaxf(M, m0);
        if (nT > 1) M = fmaxf(M, m1);
        if (nT > 2) M = fmaxf(M, m2);
        if (nT > 3) M = fmaxf(M, m3);

        // ---- phase A: compute my 2 v values -> vsm (bf16) ----
        {
            const int n   = tid >> 7;            // w row 0..3
            const int kpp = (tid & 127) << 1;    // kp pair base
            const float mn = (n == 0) ? m0 : (n == 1) ? m1 : (n == 2) ? m2 : m3;
            float v0 = 0.f, v1 = 0.f;
            if (n < j) {                         // valid transition row
                const float* rp = &sRing[(j - 1 - n) & 7][kpp];
                v0 = __expf(rp[0] - mn);
                v1 = __expf(rp[1] - mn);
            }
            __nv_bfloat162 vp = __floats2bfloat162_rn(v0, v1);
            *(uint32_t*)(vsm + n * ROWB + (kpp << 1)) = *(uint32_t*)&vp;
        }

        // ---- prefetch next step's emissions (consumed next iteration) ----
        float l0 = 0.f, l1 = 0.f, l2 = 0.f, l3 = 0.f;
        float q0 = 0.f, q1 = 0.f, q2 = 0.f, q3 = 0.f;
        if (tid < KK && (j + 1) < JMAX) {
            const size_t ei = (((size_t)b * SS + (j + 1)) * WW) * KK + tid;
            l0 = __ldg(logits + ei);          q0 = __ldg(hc + ei);
            l1 = __ldg(logits + ei + 1 * KK); q1 = __ldg(hc + ei + 1 * KK);
            l2 = __ldg(logits + ei + 2 * KK); q2 = __ldg(hc + ei + 2 * KK);
            l3 = __ldg(logits + ei + 3 * KK); q3 = __ldg(hc + ei + 3 * KK);
        }
        __syncthreads();   // v ready

        // ---- phase B: 16 chained HMMA (2 accumulator chains) ----
        float d0 = 0.f, d1 = 0.f, d2 = 0.f, d3 = 0.f;
        float f0 = 0.f, f1 = 0.f, f2 = 0.f, f3 = 0.f;
        const int      n8    = lane >> 2;                 // B column (w)
        const uint32_t bboff = (uint32_t)(lane & 3) << 2; // 4*(lane%4)
        #pragma unroll
        for (int c = 0; c < NCH; c += 2) {
            uint32_t b0 = 0, b1 = 0, b2 = 0, b3 = 0;
            if (n8 < 4) {
                const unsigned char* vp = vsm + n8 * ROWB + (c << 5) + bboff;
                b0 = *(const uint32_t*)(vp);
                b1 = *(const uint32_t*)(vp + 16);
                b2 = *(const uint32_t*)(vp + 32);
                b3 = *(const uint32_t*)(vp + 48);
            }
            MMA_BF16(d0, d1, d2, d3, A[c],     b0, b1);
            MMA_BF16(f0, f1, f2, f3, A[c + 1], b2, b3);
        }
        d0 += f0; d1 += f1; d2 += f2; d3 += f3;

        // ---- epilogue: combine w-dots into alpha (lane%4==0 lanes) ----
        float s0 = __shfl_down_sync(0xffffffffu, d0, 1);   // w2 (row r0g)
        float s1 = __shfl_down_sync(0xffffffffu, d1, 1);   // w3 (row r0g)
        float s2 = __shfl_down_sync(0xffffffffu, d2, 1);   // w2 (row r0g+8)
        float s3 = __shfl_down_sync(0xffffffffu, d3, 1);   // w3 (row r0g+8)
        float mv = -1e30f;
        if ((lane & 3) == 0) {
            const float4 eA = sE[r0g];
            const float4 eB = sE[r0g + 8];
            float totA = 0.f, totB = 0.f;
            if (nT > 0) { totA += __expf(eA.x + m0 - M) * d0;
                          totB += __expf(eB.x + m0 - M) * d2; }
            if (nT > 1) { totA += __expf(eA.y + m1 - M) * d1;
                          totB += __expf(eB.y + m1 - M) * d3; }
            if (nT > 2) { totA += __expf(eA.z + m2 - M) * s0;
                          totB += __expf(eB.z + m2 - M) * s2; }
            if (nT > 3) { totA += __expf(eA.w + m3 - M) * s1;
                          totB += __expf(eB.w + m3 - M) * s3; }
            if (j < WW) {   // initial-state (zeros) row at w == j
                float iA = (j == 0) ? eA.x : (j == 1) ? eA.y : (j == 2) ? eA.z : eA.w;
                float iB = (j == 0) ? eB.x : (j == 1) ? eB.y : (j == 2) ? eB.z : eB.w;
                totA += 256.0f * __expf(iA - M);
                totB += 256.0f * __expf(iB - M);
            }
            const float aA = M + __logf(totA);
            const float aB = M + __logf(totB);
            sRing[slot][r0g]     = aA;
            sRing[slot][r0g + 8] = aB;
            mv = fmaxf(aA, aB);
        }
        #pragma unroll
        for (int o = 16; o; o >>= 1)
            mv = fmaxf(mv, __shfl_xor_sync(0xffffffffu, mv, o));
        if (lane == 0) sRed[wid] = mv;
        __syncthreads();   // alphas + warp maxes ready

        // ---- block rowmax, shift history ----
        float rowmax;
        {
            const float4* rr = (const float4*)sRed;
            float4 x0 = rr[0], x1 = rr[1], x2 = rr[2], x3 = rr[3];
            rowmax = fmaxf(fmaxf(fmaxf(x0.x, x0.y), fmaxf(x0.z, x0.w)),
                           fmaxf(fmaxf(x1.x, x1.y), fmaxf(x1.z, x1.w)));
            rowmax = fmaxf(rowmax,
                     fmaxf(fmaxf(fmaxf(x2.x, x2.y), fmaxf(x2.z, x2.w)),
                           fmaxf(fmaxf(x3.x, x3.y), fmaxf(x3.z, x3.w))));
        }
        m3 = m2; m2 = m1; m1 = m0; m0 = rowmax;

        if (j + 1 < JMAX) {
            // stage next step's emissions
            if (tid < KK)
                sE[tid] = make_float4((l0 + q0) * tm0, (l1 + q1) * tm0,
                                      (l2 + q2) * tm0, (l3 + q3) * tm0);
        } else {
            // ---- final logsumexp over alpha row ----
            float sv = (tid < KK) ? __expf(sRing[slot][tid] - rowmax) : 0.f;
            #pragma unroll
            for (int o = 16; o; o >>= 1)
                sv += __shfl_xor_sync(0xffffffffu, sv, o);
            if (lane == 0 && wid < 8) sRed[16 + wid] = sv;
            __syncthreads();
            if (tid == 0) {
                float ssum = 0.f;
                #pragma unroll
                for (int i = 0; i < 8; i++) ssum += sRed[16 + i];
                out[b] = rowmax + __logf(ssum);
            }
        }
    }
}

// ---------------------------------------------------------------------------
extern "C" void kernel_launch(void* const* d_in, const int* in_sizes, int n_in,
                              void* d_out, int out_size) {
    const float* logits = (const float*)d_in[0];   // (B,S,W,K) f32
    const float* T      = (const float*)d_in[1];   // (B,K,K)   f32
    const float* hc     = (const float*)d_in[2];   // (B,S,W,K) f32
    const float* tagm   = (const float*)d_in[3];   // (B,K,K)   f32
    const int*   tmask  = (const int*)  d_in[4];   // (B,S)     i32
    float* out = (float*)d_out;                    // (1,B)     f32

    crf_hmma_kernel<<<BB, NT>>>(logits, T, hc, tagm, tmask, out);
}

// round 9
// speedup vs baseline: 1.5711x; 1.0110x over previous
#include <cuda_runtime.h>
#include <cuda_bf16.h>
#include <cstdint>
#include <math.h>

#define BB 48
#define SS 128
#define WW 4
#define KK 256
#define KH 128
#define NT 512
#define ROWB 520           // vsm row stride in bytes
#define TXB 544u           // 128 alphas + 8 warp maxes

typedef unsigned long long ull;

#define MMA_BF16(d0, d1, d2, d3, a, b0, b1)                                   \
    asm volatile(                                                             \
        "mma.sync.aligned.m16n8k16.row.col.f32.bf16.bf16.f32 "                \
        "{%0,%1,%2,%3}, {%4,%5,%6,%7}, {%8,%9}, {%0,%1,%2,%3};"               \
        : "+f"(d0), "+f"(d1), "+f"(d2), "+f"(d3)                              \
        : "r"((a)[0]), "r"((a)[1]), "r"((a)[2]), "r"((a)[3]),                 \
          "r"(b0), "r"(b1))

static __device__ __forceinline__ uint32_t s2u(const void* p) {
    uint32_t a;
    asm("{ .reg .u64 t; cvta.to.shared.u64 t, %1; cvt.u32.u64 %0, t; }"
        : "=r"(a) : "l"(p));
    return a;
}
static __device__ __forceinline__ uint32_t mapa_u(uint32_t a, int rk) {
    uint32_t r;
    asm("mapa.shared::cluster.u32 %0, %1, %2;" : "=r"(r) : "r"(a), "r"(rk));
    return r;
}
static __device__ __forceinline__ void mbar_init(uint32_t mb, uint32_t cnt) {
    asm volatile("mbarrier.init.shared.b64 [%0], %1;" :: "r"(mb), "r"(cnt) : "memory");
}
static __device__ __forceinline__ void mbar_arm(uint32_t mb, uint32_t tx) {
    asm volatile("mbarrier.arrive.expect_tx.shared.b64 _, [%0], %1;"
                 :: "r"(mb), "r"(tx) : "memory");
}
static __device__ __forceinline__ void st_async_f32(uint32_t dst, float v, uint32_t mb) {
    asm volatile(
        "st.async.weak.shared::cluster.mbarrier::complete_tx::bytes.f32 [%0], %1, [%2];"
        :: "r"(dst), "f"(v), "r"(mb) : "memory");
}
static __device__ __forceinline__ void wait_parity(uint32_t mb, uint32_t par) {
    asm volatile(
        "{\n\t.reg .pred P;\n\t"
        "W_%=:\n\t"
        "mbarrier.try_wait.parity.acquire.cluster.shared::cta.b64 P, [%0], %1, 0x989680;\n\t"
        "@!P bra W_%=;\n\t}"
        :: "r"(mb), "r"(par) : "memory");
}

extern "C" __global__ void __launch_bounds__(NT, 1) __cluster_dims__(2, 1, 1)
crf_hmma2_kernel(const float* __restrict__ logits,
                 const float* __restrict__ T,
                 const float* __restrict__ hc,
                 const float* __restrict__ tagm,
                 const int*   __restrict__ textmask,
                 float* __restrict__ out)
{
    __shared__ float  sRing[8][KK];        // alpha ring, full rows
    __shared__ float4 sE[KH];              // staged emissions (my M half)
    __shared__ float4 sPair[8][32];        // odd-warp partial accums
    __shared__ float  sPmax[8][8];         // peer warp maxes per slot
    __shared__ float  sRed[32];
    __shared__ ull    sMbar[8];
    __shared__ __align__(4) unsigned char vsm[4 * ROWB];   // v rows (bf16)

    const int tid  = threadIdx.x;
    const int lane = tid & 31;
    const int wid  = tid >> 5;
    const int b    = blockIdx.x >> 1;
    const int r    = blockIdx.x & 1;
    const int t    = wid >> 1;           // M-tile 0..7
    const int half = wid & 1;            // K half 0/1

    // ---- length[b] ----
    {
        int tt = (tid < SS) ? textmask[b * SS + tid] : 0;
        #pragma unroll
        for (int o = 16; o; o >>= 1) tt += __shfl_xor_sync(0xffffffffu, tt, o);
        if (lane == 0) sRed[wid] = (float)tt;
    }
    __syncthreads();
    int L = 0;
    #pragma unroll
    for (int i = 0; i < 16; i++) L += (int)sRed[i];
    __syncthreads();
    if (L == 0) { if (r == 0 && tid == 0) out[b] = logf(256.0f); return; }
    const int JMAX = (L < SS) ? L : SS;

    // ---- mbarriers + cluster handshake ----
    if (tid < 8) {
        mbar_init(s2u(&sMbar[tid]), 1);
        mbar_arm(s2u(&sMbar[tid]), TXB);
    }
    __syncthreads();
    asm volatile("barrier.cluster.arrive.aligned;" ::: "memory");
    asm volatile("barrier.cluster.wait.aligned;"   ::: "memory");

    const int      peer     = 1 - r;
    const uint32_t myMbar   = s2u(sMbar);
    const uint32_t peerRing = mapa_u(s2u(sRing), peer);
    const uint32_t peerPmax = mapa_u(s2u(sPmax), peer);
    const uint32_t peerMbar = mapa_u(myMbar, peer);

    // ---- prologue: A frags (8 K-chunks, my K half), rows rg0 / rg0+8 ----
    const size_t tb  = (size_t)b * KK * KK;
    const int    lr0 = (t << 4) + (lane >> 2);   // local row in my half
    const int    rg0 = r * KH + lr0;             // global row
    const int    kq  = (lane & 3) << 1;
    uint32_t A[8][4];
    {
        const float* Tr0 = T    + tb + (size_t)rg0 * KK;
        const float* Mr0 = tagm + tb + (size_t)rg0 * KK;
        const float* Tr1 = Tr0 + 8 * KK;
        const float* Mr1 = Mr0 + 8 * KK;
        #pragma unroll
        for (int c = 0; c < 8; c++) {
            #pragma unroll
            for (int h = 0; h < 2; h++) {
                const int kk2 = (half * 8 + c) * 16 + kq + h * 8;
                float2 t0 = *(const float2*)(Tr0 + kk2);
                float2 m0 = *(const float2*)(Mr0 + kk2);
                float2 t1 = *(const float2*)(Tr1 + kk2);
                float2 m1 = *(const float2*)(Mr1 + kk2);
                __nv_bfloat162 p0 =
                    __floats2bfloat162_rn(__expf(t0.x * m0.x), __expf(t0.y * m0.y));
                __nv_bfloat162 p1 =
                    __floats2bfloat162_rn(__expf(t1.x * m1.x), __expf(t1.y * m1.y));
                A[c][h * 2 + 0] = *(uint32_t*)&p0;
                A[c][h * 2 + 1] = *(uint32_t*)&p1;
            }
        }
    }

    // ---- stage emissions for j=0 (my half: kg = r*KH + tid, tid<128) ----
    const int   kg  = r * KH + tid;
    const float tm0 = (tid < KH) ? tagm[tb + kg] : 0.f;
    if (tid < KH) {
        const size_t ei = ((size_t)b * SS) * WW * KK + kg;
        sE[tid] = make_float4(
            (__ldg(logits + ei         ) + __ldg(hc + ei         )) * tm0,
            (__ldg(logits + ei + 1 * KK) + __ldg(hc + ei + 1 * KK)) * tm0,
            (__ldg(logits + ei + 2 * KK) + __ldg(hc + ei + 2 * KK)) * tm0,
            (__ldg(logits + ei + 3 * KK) + __ldg(hc + ei + 3 * KK)) * tm0);
    }
    float m0 = 0.f, m1 = 0.f, m2 = 0.f, m3 = 0.f;
    __syncthreads();

    for (int j = 0; j < JMAX; j++) {
        const int nT   = (j < WW) ? j : WW;
        const int slot = j & 7;

        float M = (j < WW) ? 0.0f : -1e30f;
        if (nT > 0) M = fmaxf(M, m0);
        if (nT > 1) M = fmaxf(M, m1);
        if (nT > 2) M = fmaxf(M, m2);
        if (nT > 3) M = fmaxf(M, m3);

        // ---- phase A: 2 v values per thread -> vsm (full kp range) ----
        {
            const int n   = tid >> 7;
            const int kpp = (tid & 127) << 1;
            const float mn = (n == 0) ? m0 : (n == 1) ? m1 : (n == 2) ? m2 : m3;
            float v0 = 0.f, v1 = 0.f;
            if (n < j) {
                const float* rp = &sRing[(j - 1 - n) & 7][kpp];
                v0 = __expf(rp[0] - mn);
                v1 = __expf(rp[1] - mn);
            }
            __nv_bfloat162 vp = __floats2bfloat162_rn(v0, v1);
            *(uint32_t*)(vsm + n * ROWB + (kpp << 1)) = *(uint32_t*)&vp;
        }

        // ---- prefetch next emissions (consumed next iter) ----
        float l0 = 0.f, l1 = 0.f, l2 = 0.f, l3 = 0.f;
        float q0 = 0.f, q1 = 0.f, q2 = 0.f, q3 = 0.f;
        if (tid < KH && (j + 1) < JMAX) {
            const size_t ei = (((size_t)b * SS + (j + 1)) * WW) * KK + kg;
            l0 = __ldg(logits + ei);          q0 = __ldg(hc + ei);
            l1 = __ldg(logits + ei + 1 * KK); q1 = __ldg(hc + ei + 1 * KK);
            l2 = __ldg(logits + ei + 2 * KK); q2 = __ldg(hc + ei + 2 * KK);
            l3 = __ldg(logits + ei + 3 * KK); q3 = __ldg(hc + ei + 3 * KK);
        }
        __syncthreads();   // vsm ready

        // ---- phase B: 8 HMMA (2 chains of 4) over my K half ----
        float d0 = 0.f, d1 = 0.f, d2 = 0.f, d3 = 0.f;
        float f0 = 0.f, f1 = 0.f, f2 = 0.f, f3 = 0.f;
        {
            const int      n8    = lane >> 2;
            const uint32_t bboff = (uint32_t)(lane & 3) << 2;
            #pragma unroll
            for (int c = 0; c < 8; c += 2) {
                uint32_t b0 = 0, b1 = 0, b2 = 0, b3 = 0;
                if (n8 < 4) {
                    const unsigned char* vp =
                        vsm + n8 * ROWB + ((half * 8 + c) << 5) + bboff;
                    b0 = *(const uint32_t*)(vp);
                    b1 = *(const uint32_t*)(vp + 16);
                    b2 = *(const uint32_t*)(vp + 32);
                    b3 = *(const uint32_t*)(vp + 48);
                }
                MMA_BF16(d0, d1, d2, d3, A[c],     b0, b1);
                MMA_BF16(f0, f1, f2, f3, A[c + 1], b2, b3);
            }
        }
        d0 += f0; d1 += f1; d2 += f2; d3 += f3;

        // ---- pair merge: odd warp -> smem, even warp adds ----
        if (half) sPair[t][lane] = make_float4(d0, d1, d2, d3);
        __syncthreads();
        float mv = -1e30f;
        if (!half) {
            float4 pp = sPair[t][lane];
            d0 += pp.x; d1 += pp.y; d2 += pp.z; d3 += pp.w;

            // epilogue on lane%4==0
            float s0 = __shfl_down_sync(0xffffffffu, d0, 1);
            float s1 = __shfl_down_sync(0xffffffffu, d1, 1);
            float s2 = __shfl_down_sync(0xffffffffu, d2, 1);
            float s3 = __shfl_down_sync(0xffffffffu, d3, 1);
            if ((lane & 3) == 0) {
                const float4 eA = sE[lr0];
                const float4 eB = sE[lr0 + 8];
                float totA = 0.f, totB = 0.f;
                if (nT > 0) { totA += __expf(eA.x + m0 - M) * d0;
                              totB += __expf(eB.x + m0 - M) * d2; }
                if (nT > 1) { totA += __expf(eA.y + m1 - M) * d1;
                              totB += __expf(eB.y + m1 - M) * d3; }
                if (nT > 2) { totA += __expf(eA.z + m2 - M) * s0;
                              totB += __expf(eB.z + m2 - M) * s2; }
                if (nT > 3) { totA += __expf(eA.w + m3 - M) * s1;
                              totB += __expf(eB.w + m3 - M) * s3; }
                if (j < WW) {
                    float iA = (j == 0) ? eA.x : (j == 1) ? eA.y : (j == 2) ? eA.z : eA.w;
                    float iB = (j == 0) ? eB.x : (j == 1) ? eB.y : (j == 2) ? eB.z : eB.w;
                    totA += 256.0f * __expf(iA - M);
                    totB += 256.0f * __expf(iB - M);
                }
                const float aA = M + __logf(totA);
                const float aB = M + __logf(totB);
                sRing[slot][rg0]     = aA;
                sRing[slot][rg0 + 8] = aB;
                st_async_f32(peerRing + ((uint32_t)(slot * KK + rg0)) * 4u, aA,
                             peerMbar + (uint32_t)slot * 8u);
                st_async_f32(peerRing + ((uint32_t)(slot * KK + rg0 + 8)) * 4u, aB,
                             peerMbar + (uint32_t)slot * 8u);
                mv = fmaxf(aA, aB);
            }
            #pragma unroll
            for (int o = 16; o; o >>= 1)
                mv = fmaxf(mv, __shfl_xor_sync(0xffffffffu, mv, o));
            if (lane == 0) {
                sRed[t] = mv;
                st_async_f32(peerPmax + ((uint32_t)(slot * 8 + t)) * 4u, mv,
                             peerMbar + (uint32_t)slot * 8u);
            }
        }
        __syncthreads();   // sRed + local ring half visible

        // ---- wait for peer half + maxes ----
        wait_parity(myMbar + (uint32_t)slot * 8u, (uint32_t)((j >> 3) & 1));

        float rowmax = fmaxf(fmaxf(fmaxf(sRed[0], sRed[1]), fmaxf(sRed[2], sRed[3])),
                             fmaxf(fmaxf(sRed[4], sRed[5]), fmaxf(sRed[6], sRed[7])));
        {
            const float* pm = sPmax[slot];
            rowmax = fmaxf(rowmax,
                     fmaxf(fmaxf(fmaxf(pm[0], pm[1]), fmaxf(pm[2], pm[3])),
                           fmaxf(fmaxf(pm[4], pm[5]), fmaxf(pm[6], pm[7]))));
        }
        m3 = m2; m2 = m1; m1 = m0; m0 = rowmax;

        // re-arm this slot for its next phase (peer reuses it at j+8)
        if (tid == 0) mbar_arm(myMbar + (uint32_t)slot * 8u, TXB);

        if (j + 1 < JMAX) {
            if (tid < KH)
                sE[tid] = make_float4((l0 + q0) * tm0, (l1 + q1) * tm0,
                                      (l2 + q2) * tm0, (l3 + q3) * tm0);
        } else {
            // ---- final logsumexp over full alpha row ----
            float sv = (tid < KK) ? __expf(sRing[slot][tid] - rowmax) : 0.f;
            #pragma unroll
            for (int o = 16; o; o >>= 1) sv += __shfl_xor_sync(0xffffffffu, sv, o);
            if (lane == 0 && wid < 8) sRed[16 + wid] = sv;
            __syncthreads();
            if (r == 0 && tid == 0) {
                float ssum = 0.f;
                #pragma unroll
                for (int i = 0; i < 8; i++) ssum += sRed[16 + i];
                out[b] = rowmax + __logf(ssum);
            }
        }
    }

    // no CTA exits while peer st.async may be in flight
    asm volatile("barrier.cluster.arrive.aligned;" ::: "memory");
    asm volatile("barrier.cluster.wait.aligned;"   ::: "memory");
}

// ---------------------------------------------------------------------------
extern "C" void kernel_launch(void* const* d_in, const int* in_sizes, int n_in,
                              void* d_out, int out_size) {
    const float* logits = (const float*)d_in[0];   // (B,S,W,K) f32
    const float* T      = (const float*)d_in[1];   // (B,K,K)   f32
    const float* hc     = (const float*)d_in[2];   // (B,S,W,K) f32
    const float* tagm   = (const float*)d_in[3];   // (B,K,K)   f32
    const int*   tmask  = (const int*)  d_in[4];   // (B,S)     i32
    float* out = (float*)d_out;                    // (1,B)     f32

    crf_hmma2_kernel<<<BB * 2, NT>>>(logits, T, hc, tagm, tmask, out);
}

// round 10
// speedup vs baseline: 1.8855x; 1.2002x over previous
#include <cuda_runtime.h>
#include <cuda_bf16.h>
#include <cstdint>
#include <math.h>

#define BB 48
#define SS 128
#define WW 4
#define KK 256
#define KH 128
#define NT 512
#define ROWB 520           // vsm row stride in bytes
#define TXB 544u           // 128 alphas + 8 warp maxes

typedef unsigned long long ull;

#define MMA_BF16(d0, d1, d2, d3, a, b0, b1)                                   \
    asm volatile(                                                             \
        "mma.sync.aligned.m16n8k16.row.col.f32.bf16.bf16.f32 "                \
        "{%0,%1,%2,%3}, {%4,%5,%6,%7}, {%8,%9}, {%0,%1,%2,%3};"               \
        : "+f"(d0), "+f"(d1), "+f"(d2), "+f"(d3)                              \
        : "r"((a)[0]), "r"((a)[1]), "r"((a)[2]), "r"((a)[3]),                 \
          "r"(b0), "r"(b1))

static __device__ __forceinline__ uint32_t s2u(const void* p) {
    uint32_t a;
    asm("{ .reg .u64 t; cvta.to.shared.u64 t, %1; cvt.u32.u64 %0, t; }"
        : "=r"(a) : "l"(p));
    return a;
}
static __device__ __forceinline__ uint32_t mapa_u(uint32_t a, int rk) {
    uint32_t r;
    asm("mapa.shared::cluster.u32 %0, %1, %2;" : "=r"(r) : "r"(a), "r"(rk));
    return r;
}
static __device__ __forceinline__ void mbar_init(uint32_t mb, uint32_t cnt) {
    asm volatile("mbarrier.init.shared.b64 [%0], %1;" :: "r"(mb), "r"(cnt) : "memory");
}
static __device__ __forceinline__ void mbar_arm(uint32_t mb, uint32_t tx) {
    asm volatile("mbarrier.arrive.expect_tx.shared.b64 _, [%0], %1;"
                 :: "r"(mb), "r"(tx) : "memory");
}
static __device__ __forceinline__ void st_async_f32(uint32_t dst, float v, uint32_t mb) {
    asm volatile(
        "st.async.weak.shared::cluster.mbarrier::complete_tx::bytes.f32 [%0], %1, [%2];"
        :: "r"(dst), "f"(v), "r"(mb) : "memory");
}
static __device__ __forceinline__ void wait_parity(uint32_t mb, uint32_t par) {
    asm volatile(
        "{\n\t.reg .pred P;\n\t"
        "W_%=:\n\t"
        "mbarrier.try_wait.parity.acquire.cluster.shared::cta.b64 P, [%0], %1, 0x989680;\n\t"
        "@!P bra W_%=;\n\t}"
        :: "r"(mb), "r"(par) : "memory");
}
static __device__ __forceinline__ uint32_t redux_max_u32(uint32_t v) {
    uint32_t r;
    asm("redux.sync.max.u32 %0, %1, 0xffffffff;" : "=r"(r) : "r"(v));
    return r;
}
static __device__ __forceinline__ uint32_t fkey(float f) {   // order-preserving
    uint32_t u = __float_as_uint(f);
    return (u & 0x80000000u) ? ~u : (u | 0x80000000u);
}
static __device__ __forceinline__ float funkey(uint32_t k) {
    return __uint_as_float((k & 0x80000000u) ? (k & 0x7fffffffu) : ~k);
}

extern "C" __global__ void __launch_bounds__(NT, 1) __cluster_dims__(2, 1, 1)
crf_hmma3_kernel(const float* __restrict__ logits,
                 const float* __restrict__ T,
                 const float* __restrict__ hc,
                 const float* __restrict__ tagm,
                 const int*   __restrict__ textmask,
                 float* __restrict__ out)
{
    __shared__ float  sRing[8][KK];      // alpha ring, full rows
    __shared__ float  sE[2][KH][4];      // emissions, double-buffered
    __shared__ float4 sPair[8][32];      // warps 8-15 partial accums
    __shared__ float  sPmax[8][8];       // peer warp maxes per slot
    __shared__ float  sRedL[4][8];       // local warp maxes (4-slot ring)
    __shared__ float  sSig[4];           // rowmax_{i} by i&3 (stale scales)
    __shared__ float  sTm[KH];           // tag_mask[b,0,k] local half
    __shared__ float  sRed[32];
    __shared__ ull    sMbar[8];
    __shared__ __align__(4) unsigned char vsm[4 * ROWB];

    const int tid  = threadIdx.x;
    const int lane = tid & 31;
    const int wid  = tid >> 5;
    const int b    = blockIdx.x >> 1;
    const int r    = blockIdx.x & 1;
    const int t    = wid & 7;                         // M-tile
    const int khalf = (wid < 8) ? r : (1 - r);        // my kp half (local/peer)

    // ---- length[b] ----
    {
        int tt = (tid < SS) ? textmask[b * SS + tid] : 0;
        #pragma unroll
        for (int o = 16; o; o >>= 1) tt += __shfl_xor_sync(0xffffffffu, tt, o);
        if (lane == 0) sRed[wid] = (float)tt;
    }
    __syncthreads();
    int L = 0;
    #pragma unroll
    for (int i = 0; i < 16; i++) L += (int)sRed[i];
    __syncthreads();
    if (L == 0) { if (r == 0 && tid == 0) out[b] = logf(256.0f); return; }
    const int JMAX = (L < SS) ? L : SS;

    // ---- init barriers / sSig ----
    if (tid < 8) {
        mbar_init(s2u(&sMbar[tid]), 1);
        mbar_arm(s2u(&sMbar[tid]), TXB);
    }
    if (tid < 4) sSig[tid] = 0.f;

    // ---- prologue: A frags (my kp half), rows rg0 / rg0+8 ----
    const size_t tb  = (size_t)b * KK * KK;
    const int    lr0 = (t << 4) + (lane >> 2);
    const int    rg0 = r * KH + lr0;
    const int    kq  = (lane & 3) << 1;
    uint32_t A[8][4];
    {
        const float* Tr0 = T    + tb + (size_t)rg0 * KK;
        const float* Mr0 = tagm + tb + (size_t)rg0 * KK;
        const float* Tr1 = Tr0 + 8 * KK;
        const float* Mr1 = Mr0 + 8 * KK;
        #pragma unroll
        for (int c = 0; c < 8; c++) {
            #pragma unroll
            for (int h = 0; h < 2; h++) {
                const int kk2 = (khalf * 8 + c) * 16 + kq + h * 8;
                float2 t0 = *(const float2*)(Tr0 + kk2);
                float2 m0 = *(const float2*)(Mr0 + kk2);
                float2 t1 = *(const float2*)(Tr1 + kk2);
                float2 m1 = *(const float2*)(Mr1 + kk2);
                __nv_bfloat162 p0 =
                    __floats2bfloat162_rn(__expf(t0.x * m0.x), __expf(t0.y * m0.y));
                __nv_bfloat162 p1 =
                    __floats2bfloat162_rn(__expf(t1.x * m1.x), __expf(t1.y * m1.y));
                A[c][h * 2 + 0] = *(uint32_t*)&p0;
                A[c][h * 2 + 1] = *(uint32_t*)&p1;
            }
        }
    }

    // ---- sTm + sE[0] ----
    if (tid < KH) sTm[tid] = tagm[tb + r * KH + tid];
    __syncthreads();
    if (tid < 256) {
        const int k_l = tid >> 1, wp = (tid & 1) * 2;
        const size_t ei = (((size_t)b * SS + 0) * WW + wp) * KK + (r * KH + k_l);
        const float tm = sTm[k_l];
        sE[0][k_l][wp]     = (__ldg(logits + ei     ) + __ldg(hc + ei     )) * tm;
        sE[0][k_l][wp + 1] = (__ldg(logits + ei + KK) + __ldg(hc + ei + KK)) * tm;
    }
    __syncthreads();
    asm volatile("barrier.cluster.arrive.aligned;" ::: "memory");
    asm volatile("barrier.cluster.wait.aligned;"   ::: "memory");

    const int      peer     = 1 - r;
    const uint32_t myMbar   = s2u(sMbar);
    const uint32_t peerRing = mapa_u(s2u(sRing), peer);
    const uint32_t peerPmax = mapa_u(s2u(sPmax), peer);
    const uint32_t peerMbar = mapa_u(myMbar, peer);

    // v-writer mapping (each warp group covers its kp half)
    const int vw   = wid & 7;
    const int vn   = vw & 3;                         // B row (w)
    const int vkpg = khalf * KH + (vw >> 2) * 64 + lane * 2;   // global kp pair

    float s0 = 0.f, s1 = 0.f, s2 = 0.f, s3 = 0.f;    // stale scales (newest first)

    for (int j = 0; j < JMAX; j++) {
        const int nT   = (j < WW) ? j : WW;
        const int slot = j & 7;

        // ---- shift stale scales; s0 = rowmax_{j-2} ----
        s3 = s2; s2 = s1; s1 = s0;
        s0 = (j >= 2) ? sSig[(j - 2) & 3] : 0.f;
        float M = (j < WW) ? 0.0f : -1e30f;
        if (nT > 0) M = fmaxf(M, s0);
        if (nT > 1) M = fmaxf(M, s1);
        if (nT > 2) M = fmaxf(M, s2);
        if (nT > 3) M = fmaxf(M, s3);

        float d0 = 0.f, d1 = 0.f, d2 = 0.f, d3 = 0.f;

        if (wid < 8) {
            // ===== local-kp warps: v-local -> bar1 -> MMA =====
            {
                float v0 = 0.f, v1 = 0.f;
                if (vn < j) {
                    const float sn = (vn == 0) ? s0 : (vn == 1) ? s1 : (vn == 2) ? s2 : s3;
                    float2 rd = *(const float2*)&sRing[(j - 1 - vn) & 7][vkpg];
                    v0 = __expf(rd.x - sn);
                    v1 = __expf(rd.y - sn);
                }
                __nv_bfloat162 vp = __floats2bfloat162_rn(v0, v1);
                *(uint32_t*)(vsm + vn * ROWB + (vkpg << 1)) = *(uint32_t*)&vp;
            }
            asm volatile("bar.sync 1, 256;" ::: "memory");
        } else {
            // ===== peer-kp warps: wait peer alpha -> tree -> v-peer -> bar2 -> MMA =====
            if (j > 0) {
                wait_parity(myMbar + (uint32_t)((j - 1) & 7) * 8u,
                            (uint32_t)(((j - 1) >> 3) & 1));
                if (wid == 8) {          // rowmax_{j-1} -> sSig  (off critical path)
                    float x = -1e30f;
                    if (lane < 8)       x = sRedL[(j - 1) & 3][lane];
                    else if (lane < 16) x = sPmax[(j - 1) & 7][lane - 8];
                    uint32_t kk = redux_max_u32(fkey(x));
                    if (lane == 0) sSig[(j - 1) & 3] = funkey(kk);
                }
                if (tid == 288)          // re-arm consumed slot for step j+7
                    mbar_arm(myMbar + (uint32_t)((j - 1) & 7) * 8u, TXB);
            }
            {
                float v0 = 0.f, v1 = 0.f;
                if (vn < j) {
                    const float sn = (vn == 0) ? s0 : (vn == 1) ? s1 : (vn == 2) ? s2 : s3;
                    float2 rd = *(const float2*)&sRing[(j - 1 - vn) & 7][vkpg];
                    v0 = __expf(rd.x - sn);
                    v1 = __expf(rd.y - sn);
                }
                __nv_bfloat162 vp = __floats2bfloat162_rn(v0, v1);
                *(uint32_t*)(vsm + vn * ROWB + (vkpg << 1)) = *(uint32_t*)&vp;
            }
            asm volatile("bar.sync 2, 256;" ::: "memory");
        }

        // ---- emission LDGs for j+1 (warps 8-15; land before post-M1 use) ----
        float l0 = 0.f, l1 = 0.f, q0 = 0.f, q1 = 0.f;
        int k_l = 0, wp = 0;
        if (wid >= 8 && (j + 1) < JMAX) {
            const int idx = tid & 255;
            k_l = idx >> 1; wp = (idx & 1) * 2;
            const size_t ei = (((size_t)b * SS + (j + 1)) * WW + wp) * KK + (r * KH + k_l);
            l0 = __ldg(logits + ei);      q0 = __ldg(hc + ei);
            l1 = __ldg(logits + ei + KK); q1 = __ldg(hc + ei + KK);
        }

        // ---- MMA over my kp half (8 chunks, 2 chains of 4) ----
        {
            float f0 = 0.f, f1 = 0.f, f2 = 0.f, f3 = 0.f;
            const int      n8    = lane >> 2;
            const uint32_t bboff = (uint32_t)(lane & 3) << 2;
            #pragma unroll
            for (int c = 0; c < 8; c += 2) {
                uint32_t b0 = 0, b1 = 0, b2 = 0, b3 = 0;
                if (n8 < 4) {
                    const unsigned char* vp =
                        vsm + n8 * ROWB + ((khalf * 8 + c) << 5) + bboff;
                    b0 = *(const uint32_t*)(vp);
                    b1 = *(const uint32_t*)(vp + 16);
                    b2 = *(const uint32_t*)(vp + 32);
                    b3 = *(const uint32_t*)(vp + 48);
                }
                MMA_BF16(d0, d1, d2, d3, A[c],     b0, b1);
                MMA_BF16(f0, f1, f2, f3, A[c + 1], b2, b3);
            }
            d0 += f0; d1 += f1; d2 += f2; d3 += f3;
        }

        if (wid >= 8) sPair[t][lane] = make_float4(d0, d1, d2, d3);
        __syncthreads();   // M1: partials + vsm settled

        if (wid < 8) {
            // ===== merge + epilogue =====
            float4 pp = sPair[t][lane];
            d0 += pp.x; d1 += pp.y; d2 += pp.z; d3 += pp.w;

            float sh0 = __shfl_down_sync(0xffffffffu, d0, 1);
            float sh1 = __shfl_down_sync(0xffffffffu, d1, 1);
            float sh2 = __shfl_down_sync(0xffffffffu, d2, 1);
            float sh3 = __shfl_down_sync(0xffffffffu, d3, 1);
            float mv = -1e30f;
            if ((lane & 3) == 0) {
                const float4 eA = *(const float4*)sE[j & 1][lr0];
                const float4 eB = *(const float4*)sE[j & 1][lr0 + 8];
                float totA = 0.f, totB = 0.f;
                if (nT > 0) { totA += __expf(eA.x + s0 - M) * d0;
                              totB += __expf(eB.x + s0 - M) * d2; }
                if (nT > 1) { totA += __expf(eA.y + s1 - M) * d1;
                              totB += __expf(eB.y + s1 - M) * d3; }
                if (nT > 2) { totA += __expf(eA.z + s2 - M) * sh0;
                              totB += __expf(eB.z + s2 - M) * sh2; }
                if (nT > 3) { totA += __expf(eA.w + s3 - M) * sh1;
                              totB += __expf(eB.w + s3 - M) * sh3; }
                if (j < WW) {
                    float iA = (j == 0) ? eA.x : (j == 1) ? eA.y : (j == 2) ? eA.z : eA.w;
                    float iB = (j == 0) ? eB.x : (j == 1) ? eB.y : (j == 2) ? eB.z : eB.w;
                    totA += 256.0f * __expf(iA - M);
                    totB += 256.0f * __expf(iB - M);
                }
                const float aA = M + __logf(totA);
                const float aB = M + __logf(totB);
                sRing[slot][rg0]     = aA;
                sRing[slot][rg0 + 8] = aB;
                st_async_f32(peerRing + ((uint32_t)(slot * KK + rg0)) * 4u, aA,
                             peerMbar + (uint32_t)slot * 8u);
                st_async_f32(peerRing + ((uint32_t)(slot * KK + rg0 + 8)) * 4u, aB,
                             peerMbar + (uint32_t)slot * 8u);
                mv = fmaxf(aA, aB);
            }
            uint32_t km = redux_max_u32(fkey(mv));
            if (lane == 0) {
                float wm = funkey(km);
                sRedL[j & 3][t] = wm;
                st_async_f32(peerPmax + ((uint32_t)(slot * 8 + t)) * 4u, wm,
                             peerMbar + (uint32_t)slot * 8u);
            }
        } else if ((j + 1) < JMAX) {
            // ===== emission staging into sE[(j+1)&1] =====
            const float tm = sTm[k_l];
            sE[(j + 1) & 1][k_l][wp]     = (l0 + q0) * tm;
            sE[(j + 1) & 1][k_l][wp + 1] = (l1 + q1) * tm;
        }
        __syncthreads();   // S2: ring row j local + sE visible
    }

    // ---- final: wait last peer flight, then logsumexp over full row ----
    if (wid >= 8)
        wait_parity(myMbar + (uint32_t)((JMAX - 1) & 7) * 8u,
                    (uint32_t)(((JMAX - 1) >> 3) & 1));
    __syncthreads();
    {
        const int fslot = (JMAX - 1) & 7;
        float a = (tid < KK) ? sRing[fslot][tid] : -1e30f;
        uint32_t km = redux_max_u32(fkey(a));
        if (lane == 0 && wid < 8) sRed[wid] = funkey(km);
        __syncthreads();
        float rowmax = sRed[0];
        #pragma unroll
        for (int i = 1; i < 8; i++) rowmax = fmaxf(rowmax, sRed[i]);
        float sv = (tid < KK) ? __expf(a - rowmax) : 0.f;
        #pragma unroll
        for (int o = 16; o; o >>= 1) sv += __shfl_xor_sync(0xffffffffu, sv, o);
        if (lane == 0 && wid < 8) sRed[8 + wid] = sv;
        __syncthreads();
        if (r == 0 && tid == 0) {
            float ssum = 0.f;
            #pragma unroll
            for (int i = 0; i < 8; i++) ssum += sRed[8 + i];
            out[b] = rowmax + __logf(ssum);
        }
    }

    asm volatile("barrier.cluster.arrive.aligned;" ::: "memory");
    asm volatile("barrier.cluster.wait.aligned;"   ::: "memory");
}

// ---------------------------------------------------------------------------
extern "C" void kernel_launch(void* const* d_in, const int* in_sizes, int n_in,
                              void* d_out, int out_size) {
    const float* logits = (const float*)d_in[0];   // (B,S,W,K) f32
    const float* T      = (const float*)d_in[1];   // (B,K,K)   f32
    const float* hc     = (const float*)d_in[2];   // (B,S,W,K) f32
    const float* tagm   = (const float*)d_in[3];   // (B,K,K)   f32
    const int*   tmask  = (const int*)  d_in[4];   // (B,S)     i32
    float* out = (float*)d_out;                    // (1,B)     f32

    crf_hmma3_kernel<<<BB * 2, NT>>>(logits, T, hc, tagm, tmask, out);
}

// round 11
// speedup vs baseline: 1.9680x; 1.0438x over previous
#include <cuda_runtime.h>
#include <cuda_bf16.h>
#include <cstdint>
#include <math.h>

#define BB 48
#define SS 128
#define WW 4
#define KK 256
#define KH 128
#define NT 512
#define ROWB 520           // vsm row stride in bytes
#define TXB 544u           // 128 alphas + 8 warp maxes

typedef unsigned long long ull;

#define MMA_BF16(d0, d1, d2, d3, a, b0, b1)                                   \
    asm volatile(                                                             \
        "mma.sync.aligned.m16n8k16.row.col.f32.bf16.bf16.f32 "                \
        "{%0,%1,%2,%3}, {%4,%5,%6,%7}, {%8,%9}, {%0,%1,%2,%3};"               \
        : "+f"(d0), "+f"(d1), "+f"(d2), "+f"(d3)                              \
        : "r"((a)[0]), "r"((a)[1]), "r"((a)[2]), "r"((a)[3]),                 \
          "r"(b0), "r"(b1))

static __device__ __forceinline__ uint32_t s2u(const void* p) {
    uint32_t a;
    asm("{ .reg .u64 t; cvta.to.shared.u64 t, %1; cvt.u32.u64 %0, t; }"
        : "=r"(a) : "l"(p));
    return a;
}
static __device__ __forceinline__ uint32_t mapa_u(uint32_t a, int rk) {
    uint32_t r;
    asm("mapa.shared::cluster.u32 %0, %1, %2;" : "=r"(r) : "r"(a), "r"(rk));
    return r;
}
static __device__ __forceinline__ void mbar_init(uint32_t mb, uint32_t cnt) {
    asm volatile("mbarrier.init.shared.b64 [%0], %1;" :: "r"(mb), "r"(cnt) : "memory");
}
static __device__ __forceinline__ void mbar_arm(uint32_t mb, uint32_t tx) {
    asm volatile("mbarrier.arrive.expect_tx.shared.b64 _, [%0], %1;"
                 :: "r"(mb), "r"(tx) : "memory");
}
static __device__ __forceinline__ void st_async_f32(uint32_t dst, float v, uint32_t mb) {
    asm volatile(
        "st.async.weak.shared::cluster.mbarrier::complete_tx::bytes.f32 [%0], %1, [%2];"
        :: "r"(dst), "f"(v), "r"(mb) : "memory");
}
static __device__ __forceinline__ void wait_parity(uint32_t mb, uint32_t par) {
    asm volatile(
        "{\n\t.reg .pred P;\n\t"
        "W_%=:\n\t"
        "mbarrier.try_wait.parity.acquire.cluster.shared::cta.b64 P, [%0], %1, 0x989680;\n\t"
        "@!P bra W_%=;\n\t}"
        :: "r"(mb), "r"(par) : "memory");
}
static __device__ __forceinline__ uint32_t redux_max_u32(uint32_t v) {
    uint32_t r;
    asm("redux.sync.max.u32 %0, %1, 0xffffffff;" : "=r"(r) : "r"(v));
    return r;
}
static __device__ __forceinline__ uint32_t fkey(float f) {   // order-preserving
    uint32_t u = __float_as_uint(f);
    return (u & 0x80000000u) ? ~u : (u | 0x80000000u);
}
static __device__ __forceinline__ float funkey(uint32_t k) {
    return __uint_as_float((k & 0x80000000u) ? (k & 0x7fffffffu) : ~k);
}

extern "C" __global__ void __launch_bounds__(NT, 1) __cluster_dims__(2, 1, 1)
crf_hmma4_kernel(const float* __restrict__ logits,
                 const float* __restrict__ T,
                 const float* __restrict__ hc,
                 const float* __restrict__ tagm,
                 const int*   __restrict__ textmask,
                 float* __restrict__ out)
{
    __shared__ float  sRing[8][KK];       // alpha ring, full rows
    __shared__ float  sE[2][KH][4];       // emissions, double-buffered
    __shared__ float4 sPair[2][8][32];    // group B partials, double-buffered
    __shared__ float  sPmax[8][8];        // peer warp maxes per slot
    __shared__ float  sRedL[4][8];        // local warp maxes (4-slot ring)
    __shared__ float  sTm[KH];            // tag_mask[b,0,k] local half
    __shared__ float  sRed[32];
    __shared__ ull    sMbar[8];
    __shared__ __align__(4) unsigned char vsm[4 * ROWB];

    const int tid  = threadIdx.x;
    const int lane = tid & 31;
    const int wid  = tid >> 5;
    const int b    = blockIdx.x >> 1;
    const int r    = blockIdx.x & 1;
    const int t    = wid & 7;                         // M-tile
    const int khalf = (wid < 8) ? r : (1 - r);        // my kp half

    // ---- length[b] ----
    {
        int tt = (tid < SS) ? textmask[b * SS + tid] : 0;
        #pragma unroll
        for (int o = 16; o; o >>= 1) tt += __shfl_xor_sync(0xffffffffu, tt, o);
        if (lane == 0) sRed[wid] = (float)tt;
    }
    __syncthreads();
    int L = 0;
    #pragma unroll
    for (int i = 0; i < 16; i++) L += (int)sRed[i];
    __syncthreads();
    if (L == 0) { if (r == 0 && tid == 0) out[b] = logf(256.0f); return; }
    const int JMAX = (L < SS) ? L : SS;

    // ---- init barriers ----
    if (tid < 8) {
        mbar_init(s2u(&sMbar[tid]), 1);
        mbar_arm(s2u(&sMbar[tid]), TXB);
    }

    // ---- prologue: A frags (my kp half), rows rg0 / rg0+8 ----
    const size_t tb  = (size_t)b * KK * KK;
    const int    lr0 = (t << 4) + (lane >> 2);
    const int    rg0 = r * KH + lr0;
    const int    kq  = (lane & 3) << 1;
    uint32_t A[8][4];
    {
        const float* Tr0 = T    + tb + (size_t)rg0 * KK;
        const float* Mr0 = tagm + tb + (size_t)rg0 * KK;
        const float* Tr1 = Tr0 + 8 * KK;
        const float* Mr1 = Mr0 + 8 * KK;
        #pragma unroll
        for (int c = 0; c < 8; c++) {
            #pragma unroll
            for (int h = 0; h < 2; h++) {
                const int kk2 = (khalf * 8 + c) * 16 + kq + h * 8;
                float2 t0 = *(const float2*)(Tr0 + kk2);
                float2 m0 = *(const float2*)(Mr0 + kk2);
                float2 t1 = *(const float2*)(Tr1 + kk2);
                float2 m1 = *(const float2*)(Mr1 + kk2);
                __nv_bfloat162 p0 =
                    __floats2bfloat162_rn(__expf(t0.x * m0.x), __expf(t0.y * m0.y));
                __nv_bfloat162 p1 =
                    __floats2bfloat162_rn(__expf(t1.x * m1.x), __expf(t1.y * m1.y));
                A[c][h * 2 + 0] = *(uint32_t*)&p0;
                A[c][h * 2 + 1] = *(uint32_t*)&p1;
            }
        }
    }

    // ---- sTm + sE[0] ----
    if (tid < KH) sTm[tid] = tagm[tb + r * KH + tid];
    __syncthreads();
    if (tid < 256) {
        const int k_l = tid >> 1, wp = (tid & 1) * 2;
        const size_t ei = (((size_t)b * SS + 0) * WW + wp) * KK + (r * KH + k_l);
        const float tm = sTm[k_l];
        sE[0][k_l][wp]     = (__ldg(logits + ei     ) + __ldg(hc + ei     )) * tm;
        sE[0][k_l][wp + 1] = (__ldg(logits + ei + KK) + __ldg(hc + ei + KK)) * tm;
    }
    __syncthreads();
    asm volatile("barrier.cluster.arrive.aligned;" ::: "memory");
    asm volatile("barrier.cluster.wait.aligned;"   ::: "memory");

    const int      peer     = 1 - r;
    const uint32_t myMbar   = s2u(sMbar);
    const uint32_t peerRing = mapa_u(s2u(sRing), peer);
    const uint32_t peerPmax = mapa_u(s2u(sPmax), peer);
    const uint32_t peerMbar = mapa_u(myMbar, peer);

    // v-writer mapping
    const int vw   = wid & 7;
    const int vn   = vw & 3;                                   // B row (w)
    const int vkpg = khalf * KH + (vw >> 2) * 64 + lane * 2;   // global kp pair
    const uint32_t vdst = (uint32_t)(vn * ROWB + (vkpg << 1)); // vsm byte offset

    float s0 = 0.f, s1 = 0.f, s2 = 0.f, s3 = 0.f;   // stale scales (newest first)

    for (int j = 0; j < JMAX; j++) {
        const int nT   = (j < WW) ? j : WW;
        const int slot = j & 7;

        if (wid < 8) asm volatile("bar.sync 1, 256;" ::: "memory");

        // ---- stale scale: rowmax_{j-2} via per-warp redux ----
        float ns = 0.f;
        if (j >= 2) {
            float x = -1e30f;
            if (lane < 8)       x = sRedL[(j - 2) & 3][lane];
            else if (lane < 16) x = sPmax[(j - 2) & 7][lane - 8];
            ns = funkey(redux_max_u32(fkey(x)));
        }
        s3 = s2; s2 = s1; s1 = s0; s0 = ns;
        float M = (j < WW) ? 0.0f : -1e30f;
        if (nT > 0) M = fmaxf(M, s0);
        if (nT > 1) M = fmaxf(M, s1);
        if (nT > 2) M = fmaxf(M, s2);
        if (nT > 3) M = fmaxf(M, s3);

        float d0 = 0.f, d1 = 0.f, d2 = 0.f, d3 = 0.f;

        if (wid < 8) {
            // ===== group A: v-local -> bar1 -> MMA =====
            float v0 = 0.f, v1 = 0.f;
            if (vn < j) {
                const float sn = (vn == 0) ? s0 : (vn == 1) ? s1 : (vn == 2) ? s2 : s3;
                float2 rd = *(const float2*)&sRing[(j - 1 - vn) & 7][vkpg];
                v0 = __expf(rd.x - sn);
                v1 = __expf(rd.y - sn);
            }
            __nv_bfloat162 vp = __floats2bfloat162_rn(v0, v1);
            *(uint32_t*)(vsm + vdst) = *(uint32_t*)&vp;
            asm volatile("bar.sync 1, 256;" ::: "memory");
        } else {
            // ===== group B: wait peer alpha (overlaps group A's prior epilogue) =====
            if (j > 0) {
                wait_parity(myMbar + (uint32_t)((j - 1) & 7) * 8u,
                            (uint32_t)(((j - 1) >> 3) & 1));
                if (tid == 288)   // re-arm consumed slot for step j+7
                    mbar_arm(myMbar + (uint32_t)((j - 1) & 7) * 8u, TXB);
            }
            float v0 = 0.f, v1 = 0.f;
            if (vn < j) {
                const float sn = (vn == 0) ? s0 : (vn == 1) ? s1 : (vn == 2) ? s2 : s3;
                float2 rd = *(const float2*)&sRing[(j - 1 - vn) & 7][vkpg];
                v0 = __expf(rd.x - sn);
                v1 = __expf(rd.y - sn);
            }
            __nv_bfloat162 vp = __floats2bfloat162_rn(v0, v1);
            *(uint32_t*)(vsm + vdst) = *(uint32_t*)&vp;
            asm volatile("bar.sync 2, 256;" ::: "memory");
        }

        // ---- emission LDGs for j+1 (group B) ----
        float l0 = 0.f, l1 = 0.f, q0 = 0.f, q1 = 0.f;
        int k_l = 0, wp = 0;
        if (wid >= 8 && (j + 1) < JMAX) {
            const int idx = tid & 255;
            k_l = idx >> 1; wp = (idx & 1) * 2;
            const size_t ei = (((size_t)b * SS + (j + 1)) * WW + wp) * KK + (r * KH + k_l);
            l0 = __ldg(logits + ei);      q0 = __ldg(hc + ei);
            l1 = __ldg(logits + ei + KK); q1 = __ldg(hc + ei + KK);
        }

        // ---- MMA over my kp half (8 chunks, 2 chains of 4) ----
        {
            float f0 = 0.f, f1 = 0.f, f2 = 0.f, f3 = 0.f;
            const int      n8    = lane >> 2;
            const uint32_t bboff = (uint32_t)(lane & 3) << 2;
            #pragma unroll
            for (int c = 0; c < 8; c += 2) {
                uint32_t b0 = 0, b1 = 0, b2 = 0, b3 = 0;
                if (n8 < 4) {
                    const unsigned char* vp =
                        vsm + n8 * ROWB + ((khalf * 8 + c) << 5) + bboff;
                    b0 = *(const uint32_t*)(vp);
                    b1 = *(const uint32_t*)(vp + 16);
                    b2 = *(const uint32_t*)(vp + 32);
                    b3 = *(const uint32_t*)(vp + 48);
                }
                MMA_BF16(d0, d1, d2, d3, A[c],     b0, b1);
                MMA_BF16(f0, f1, f2, f3, A[c + 1], b2, b3);
            }
            d0 += f0; d1 += f1; d2 += f2; d3 += f3;
        }

        if (wid >= 8) sPair[j & 1][t][lane] = make_float4(d0, d1, d2, d3);
        __syncthreads();   // M1

        if (wid < 8) {
            // ===== merge + split epilogue =====
            float4 pp = sPair[j & 1][t][lane];
            d0 += pp.x; d1 += pp.y; d2 += pp.z; d3 += pp.w;

            const int sub = lane & 3;
            float pA = 0.f, pB = 0.f;
            if (sub < 2) {
                const float4 eA4 = *(const float4*)sE[j & 1][lr0];
                const float4 eB4 = *(const float4*)sE[j & 1][lr0 + 8];
                const float ea0 = sub ? eA4.z : eA4.x;
                const float ea1 = sub ? eA4.w : eA4.y;
                const float eb0 = sub ? eB4.z : eB4.x;
                const float eb1 = sub ? eB4.w : eB4.y;
                const float sc0 = sub ? s2 : s0;
                const float sc1 = sub ? s3 : s1;
                const int   w0i = sub << 1;
                if (nT > w0i) {
                    float xA = __expf(ea0 + sc0 - M), xB = __expf(eb0 + sc0 - M);
                    pA += xA * d0;  pB += xB * d2;
                }
                if (nT > w0i + 1) {
                    float xA = __expf(ea1 + sc1 - M), xB = __expf(eb1 + sc1 - M);
                    pA += xA * d1;  pB += xB * d3;
                }
                if (j < WW && (j >> 1) == sub) {   // initial-state (zeros) row
                    float ia = (j & 1) ? ea1 : ea0;
                    float ib = (j & 1) ? eb1 : eb0;
                    pA += 256.0f * __expf(ia - M);
                    pB += 256.0f * __expf(ib - M);
                }
            }
            pA += __shfl_down_sync(0xffffffffu, pA, 1);
            pB += __shfl_down_sync(0xffffffffu, pB, 1);

            float mv = -1e30f;
            if (sub == 0) {
                const float aA = M + __logf(pA);
                const float aB = M + __logf(pB);
                sRing[slot][rg0]     = aA;
                sRing[slot][rg0 + 8] = aB;
                st_async_f32(peerRing + ((uint32_t)(slot * KK + rg0)) * 4u, aA,
                             peerMbar + (uint32_t)slot * 8u);
                st_async_f32(peerRing + ((uint32_t)(slot * KK + rg0 + 8)) * 4u, aB,
                             peerMbar + (uint32_t)slot * 8u);
                mv = fmaxf(aA, aB);
            }
            uint32_t km = redux_max_u32(fkey(mv));
            if (lane == 0) {
                const float wm = funkey(km);
                sRedL[j & 3][t] = wm;
                st_async_f32(peerPmax + ((uint32_t)(slot * 8 + t)) * 4u, wm,
                             peerMbar + (uint32_t)slot * 8u);
            }
        } else if ((j + 1) < JMAX) {
            // ===== group B: stage next emissions =====
            const float tm = sTm[k_l];
            sE[(j + 1) & 1][k_l][wp]     = (l0 + q0) * tm;
            sE[(j + 1) & 1][k_l][wp + 1] = (l1 + q1) * tm;
        }
        // no trailing sync: group B proceeds straight to next wait_parity
    }

    // ---- final: wait last peer flight, then logsumexp over full row ----
    if (wid >= 8)
        wait_parity(myMbar + (uint32_t)((JMAX - 1) & 7) * 8u,
                    (uint32_t)(((JMAX - 1) >> 3) & 1));
    __syncthreads();
    {
        const int fslot = (JMAX - 1) & 7;
        float x = -1e30f;
        if (lane < 8)       x = sRedL[(JMAX - 1) & 3][lane];
        else if (lane < 16) x = sPmax[fslot][lane - 8];
        const float rowmax = funkey(redux_max_u32(fkey(x)));

        float sv = (tid < KK) ? __expf(sRing[fslot][tid] - rowmax) : 0.f;
        #pragma unroll
        for (int o = 16; o; o >>= 1) sv += __shfl_xor_sync(0xffffffffu, sv, o);
        if (lane == 0 && wid < 8) sRed[8 + wid] = sv;
        __syncthreads();
        if (r == 0 && tid == 0) {
            float ssum = 0.f;
            #pragma unroll
            for (int i = 0; i < 8; i++) ssum += sRed[8 + i];
            out[b] = rowmax + __logf(ssum);
        }
    }

    asm volatile("barrier.cluster.arrive.aligned;" ::: "memory");
    asm volatile("barrier.cluster.wait.aligned;"   ::: "memory");
}

// ---------------------------------------------------------------------------
extern "C" void kernel_launch(void* const* d_in, const int* in_sizes, int n_in,
                              void* d_out, int out_size) {
    const float* logits = (const float*)d_in[0];   // (B,S,W,K) f32
    const float* T      = (const float*)d_in[1];   // (B,K,K)   f32
    const float* hc     = (const float*)d_in[2];   // (B,S,W,K) f32
    const float* tagm   = (const float*)d_in[3];   // (B,K,K)   f32
    const int*   tmask  = (const int*)  d_in[4];   // (B,S)     i32
    float* out = (float*)d_out;                    // (1,B)     f32

    crf_hmma4_kernel<<<BB * 2, NT>>>(logits, T, hc, tagm, tmask, out);
}